// round 9
// baseline (speedup 1.0000x reference)
#include <cuda_runtime.h>
#include <cuda_bf16.h>
#include <math.h>
#include <stdint.h>

#define V_NODES 500000
#define VD 256
#define G_NUM 4000
#define H_HEADS 8
#define GD 256
#define HID 128
#define TM 128
#define NT 512

#define PGA  132   // A1 row pitch in 8B granules (128 k-pairs + 4 pad)
#define PGA2 68    // A2 row pitch (64 k-pairs + 4 pad)
#define SMEM_MAIN   (128 * PGA * 8)                    // 135168
#define OFF_SR2     (128 * PGA2 * 8)                   // 69632
#define SMEM_TRANS2 (OFF_SR2 + 128 * 132 * 4)          // 137216

// -------- device scratch --------
__device__ float g_scores[(size_t)V_NODES * H_HEADS];
__device__ float g_m[G_NUM * H_HEADS];
__device__ float g_d[G_NUM * H_HEADS];
__device__ int   g_start_arr[G_NUM + 1];
// hidden_t = relu(E @ W1t) as hi/lo bf16 pairs, phase2-A fragment layout
__device__ uint2 g_hidden[(size_t)V_NODES * 64];
// frag-ordered weight images: entry (ks,n,c) = {bh0, bl0, bh1, bl1}
__device__ uint4 g_b1s[16 * 128 * 4];
__device__ uint4 g_b1t[16 * 128 * 4];
__device__ uint4 g_b2t[2 * 8 * 128 * 4];

// -------- helpers --------
static __device__ __forceinline__ uint32_t smem_u32(const void* p) {
    uint32_t a;
    asm("{ .reg .u64 t; cvta.to.shared.u64 t, %1; cvt.u32.u64 %0, t; }" : "=r"(a) : "l"(p));
    return a;
}
static __device__ __forceinline__ void lds64(uint32_t& a, uint32_t& b, uint32_t addr) {
    asm volatile("ld.shared.v2.b32 {%0,%1}, [%2];" : "=r"(a), "=r"(b) : "r"(addr));
}
static __device__ __forceinline__ void sts64(uint32_t addr, uint32_t a, uint32_t b) {
    asm volatile("st.shared.v2.b32 [%0], {%1,%2};" :: "r"(addr), "r"(a), "r"(b) : "memory");
}
static __device__ __forceinline__ void cpa16(uint32_t s, const void* g) {
    asm volatile("{ .reg .u64 gp; cvta.to.global.u64 gp, %1; "
                 "cp.async.cg.shared.global [%0], [gp], 16; }"
                 :: "r"(s), "l"(g) : "memory");
}
#define CP_COMMIT() asm volatile("cp.async.commit_group;" ::: "memory")
#define CP_WAIT0()  asm volatile("cp.async.wait_group 0;" ::: "memory")

static __device__ __forceinline__ void split2(float x0, float x1, uint32_t& h, uint32_t& l) {
    __nv_bfloat16 h0 = __float2bfloat16(x0), h1 = __float2bfloat16(x1);
    float r0 = x0 - __bfloat162float(h0);
    float r1 = x1 - __bfloat162float(h1);
    __nv_bfloat16 l0 = __float2bfloat16(r0), l1 = __float2bfloat16(r1);
    h = (uint32_t)__bfloat16_as_ushort(h0) | ((uint32_t)__bfloat16_as_ushort(h1) << 16);
    l = (uint32_t)__bfloat16_as_ushort(l0) | ((uint32_t)__bfloat16_as_ushort(l1) << 16);
}
static __device__ __forceinline__ void mma16816(float* d, const uint32_t* a,
                                                uint32_t b0, uint32_t b1) {
    asm volatile("mma.sync.aligned.m16n8k16.row.col.f32.bf16.bf16.f32 "
                 "{%0,%1,%2,%3}, {%4,%5,%6,%7}, {%8,%9}, {%0,%1,%2,%3};"
                 : "+f"(d[0]), "+f"(d[1]), "+f"(d[2]), "+f"(d[3])
                 : "r"(a[0]), "r"(a[1]), "r"(a[2]), "r"(a[3]), "r"(b0), "r"(b1));
}

// Dual-accumulate GEMM: one pass over A fragments (smem), two B images (LDG)
// feeding two accumulator sets. Warp computes 32x32 per output.
template<int NKS, int PG, int SWZ>
static __device__ __forceinline__ void gemm_dual(uint32_t aB,
                                                 const uint4* __restrict__ b0img,
                                                 const uint4* __restrict__ b1img,
                                                 float (&acc0)[2][4][4],
                                                 float (&acc1)[2][4][4],
                                                 int lane, int warpM, int warpN) {
    const int g = lane >> 2, c = lane & 3;
    const uint4* bp0 = b0img + ((warpN * 32 + g) * 4 + c);
    const uint4* bp1 = b1img + ((warpN * 32 + g) * 4 + c);
    const uint32_t aRow = aB + (uint32_t)((warpM * 32 + g) * PG) * 8u;
#pragma unroll
    for (int ks = 0; ks < NKS; ++ks) {
        const int x = SWZ ? (ks >> 2) : 0;
        const uint32_t j = (uint32_t)(((ks * 8) + c) ^ x) * 8u;
        uint32_t ah[2][4], al[2][4];
#pragma unroll
        for (int mt = 0; mt < 2; ++mt) {
            uint32_t base = aRow + j + (uint32_t)(mt * PG * 128);
            lds64(ah[mt][0], al[mt][0], base);
            lds64(ah[mt][1], al[mt][1], base + (uint32_t)PG * 64u);
            lds64(ah[mt][2], al[mt][2], base + 32u);
            lds64(ah[mt][3], al[mt][3], base + (uint32_t)PG * 64u + 32u);
        }
        {
            uint4 b[4];
#pragma unroll
            for (int nt = 0; nt < 4; ++nt) b[nt] = __ldg(bp0 + ks * 512 + nt * 32);
#pragma unroll
            for (int nt = 0; nt < 4; ++nt)
#pragma unroll
                for (int mt = 0; mt < 2; ++mt) {
                    mma16816(acc0[mt][nt], ah[mt], b[nt].x, b[nt].z);
                    mma16816(acc0[mt][nt], ah[mt], b[nt].y, b[nt].w);
                    mma16816(acc0[mt][nt], al[mt], b[nt].x, b[nt].z);
                }
        }
        {
            uint4 b[4];
#pragma unroll
            for (int nt = 0; nt < 4; ++nt) b[nt] = __ldg(bp1 + ks * 512 + nt * 32);
#pragma unroll
            for (int nt = 0; nt < 4; ++nt)
#pragma unroll
                for (int mt = 0; mt < 2; ++mt) {
                    mma16816(acc1[mt][nt], ah[mt], b[nt].x, b[nt].z);
                    mma16816(acc1[mt][nt], ah[mt], b[nt].y, b[nt].w);
                    mma16816(acc1[mt][nt], al[mt], b[nt].x, b[nt].z);
                }
        }
    }
}

// stage full 128x256 E tile as interleaved hi/lo pairs, conflict-free XOR layout
static __device__ __forceinline__ void stageE(const float* __restrict__ E, int m0,
                                              uint32_t aB, int tid) {
    int r = tid >> 2, q4 = tid & 3;
    bool ok = (m0 + r) < V_NODES;
    const float4* src = (const float4*)(E + (size_t)(m0 + r) * VD + q4 * 64);
    uint32_t base = aB + (uint32_t)(r * PGA) * 8u;
#pragma unroll
    for (int t = 0; t < 16; ++t) {
        float4 v = ok ? src[t] : make_float4(0.f, 0.f, 0.f, 0.f);
        int j0 = q4 * 32 + 2 * t;
        uint32_t h, l;
        split2(v.x, v.y, h, l);
        sts64(base + (uint32_t)(j0 ^ q4) * 8u, h, l);
        split2(v.z, v.w, h, l);
        sts64(base + (uint32_t)((j0 + 1) ^ q4) * 8u, h, l);
    }
}

// -------- trivial kernels --------
__global__ void k_zero(float* __restrict__ out, int n) {
    int i = blockIdx.x * blockDim.x + threadIdx.x;
    if (i < n) out[i] = 0.0f;
}
__global__ void k_offsets(const int* __restrict__ map) {
    int v = blockIdx.x * blockDim.x + threadIdx.x;
    if (v >= V_NODES) return;
    int m = map[v];
    int prev = (v == 0) ? -1 : map[v - 1];
    for (int g = prev + 1; g <= m; ++g) g_start_arr[g] = v;
    if (v == V_NODES - 1)
        for (int g = m + 1; g <= G_NUM; ++g) g_start_arr[g] = V_NODES;
}

// build frag-ordered hi/lo bf16 weight images
__global__ void k_prep(const float* __restrict__ sw1,
                       const float* __restrict__ tw1,
                       const float* __restrict__ tw2) {
    int i = blockIdx.x * blockDim.x + threadIdx.x;
    if (i >= 8192) return;
    int ks = i >> 9, n = (i >> 2) & 127, c = i & 3;
    int k0 = ks * 16 + 2 * c;
    uint4 e;
    split2(sw1[(size_t)k0 * HID + n], sw1[(size_t)(k0 + 1) * HID + n], e.x, e.y);
    split2(sw1[(size_t)(k0 + 8) * HID + n], sw1[(size_t)(k0 + 9) * HID + n], e.z, e.w);
    g_b1s[i] = e;
    split2(tw1[(size_t)k0 * HID + n], tw1[(size_t)(k0 + 1) * HID + n], e.x, e.y);
    split2(tw1[(size_t)(k0 + 8) * HID + n], tw1[(size_t)(k0 + 9) * HID + n], e.z, e.w);
    g_b1t[i] = e;
    int half = i >> 12, ks2 = (i >> 9) & 7;
    int ng = half * 128 + n, k2 = ks2 * 16 + 2 * c;
    split2(tw2[(size_t)k2 * GD + ng], tw2[(size_t)(k2 + 1) * GD + ng], e.x, e.y);
    split2(tw2[(size_t)(k2 + 8) * GD + ng], tw2[(size_t)(k2 + 9) * GD + ng], e.z, e.w);
    g_b2t[i] = e;
}

// -------- fused: scores + hidden_t (single A pass, dual accumulators) --------
__global__ void __launch_bounds__(NT, 1) k_main(const float* __restrict__ E,
                                                const float* __restrict__ W2s) {
    extern __shared__ uint8_t smemraw[];
    uint32_t sb = smem_u32(smemraw);
    __shared__ float sW2[HID * 8];
    __shared__ float sScore[TM * 8];
    int tid = threadIdx.x;
    int m0 = blockIdx.x * TM;
    for (int i = tid; i < HID * 8; i += NT) sW2[i] = W2s[i];
    for (int i = tid; i < TM * 8; i += NT) sScore[i] = 0.f;

    stageE(E, m0, sb, tid);

    int lane = tid & 31, wid = tid >> 5, warpM = wid >> 2, warpN = wid & 3;
    int g = lane >> 2, cc = lane & 3;

    float accT[2][4][4], accS[2][4][4];
#pragma unroll
    for (int a = 0; a < 2; ++a)
#pragma unroll
        for (int b = 0; b < 4; ++b)
#pragma unroll
            for (int q = 0; q < 4; ++q) { accT[a][b][q] = 0.f; accS[a][b][q] = 0.f; }
    __syncthreads();

    gemm_dual<16, PGA, 1>(sb, g_b1t, g_b1s, accT, accS, lane, warpM, warpN);

    // ---- hidden_t = relu(accT) -> g_hidden (phase2 frag layout) ----
#pragma unroll
    for (int mt = 0; mt < 2; ++mt)
#pragma unroll
        for (int i2 = 0; i2 < 2; ++i2) {
            int v = m0 + warpM * 32 + mt * 16 + i2 * 8 + g;
            if (v < V_NODES) {
#pragma unroll
                for (int nt = 0; nt < 4; ++nt) {
                    int g2 = warpN * 16 + nt * 4 + cc;
                    float x0 = fmaxf(accT[mt][nt][2 * i2], 0.f);
                    float x1 = fmaxf(accT[mt][nt][2 * i2 + 1], 0.f);
                    uint2 hl;
                    split2(x0, x1, hl.x, hl.y);
                    g_hidden[(size_t)v * 64 + g2] = hl;
                }
            }
        }

    // ---- scores = relu(accS) @ W2s ----
    float p[4][8];
#pragma unroll
    for (int r = 0; r < 4; ++r)
#pragma unroll
        for (int h = 0; h < 8; ++h) p[r][h] = 0.f;
#pragma unroll
    for (int mt = 0; mt < 2; ++mt)
#pragma unroll
        for (int nt = 0; nt < 4; ++nt) {
            int c0 = warpN * 32 + nt * 8 + cc * 2;
            float v0 = fmaxf(accS[mt][nt][0], 0.f), v1 = fmaxf(accS[mt][nt][1], 0.f);
            float v2 = fmaxf(accS[mt][nt][2], 0.f), v3 = fmaxf(accS[mt][nt][3], 0.f);
#pragma unroll
            for (int h = 0; h < 8; ++h) {
                p[mt * 2 + 0][h] += v0 * sW2[c0 * 8 + h] + v1 * sW2[c0 * 8 + 8 + h];
                p[mt * 2 + 1][h] += v2 * sW2[c0 * 8 + h] + v3 * sW2[c0 * 8 + 8 + h];
            }
        }
#pragma unroll
    for (int off = 1; off <= 2; off <<= 1)
#pragma unroll
        for (int r = 0; r < 4; ++r)
#pragma unroll
            for (int h = 0; h < 8; ++h)
                p[r][h] += __shfl_xor_sync(0xFFFFFFFFu, p[r][h], off);
    if (cc == 0) {
#pragma unroll
        for (int mt = 0; mt < 2; ++mt)
#pragma unroll
            for (int i2 = 0; i2 < 2; ++i2) {
                int row = warpM * 32 + mt * 16 + i2 * 8 + g;
#pragma unroll
                for (int h = 0; h < 8; ++h)
                    atomicAdd(&sScore[row * 8 + h], p[mt * 2 + i2][h]);
            }
    }
    __syncthreads();
    for (int i = tid; i < TM * 8; i += NT) {
        int v = m0 + (i >> 3);
        if (v < V_NODES) g_scores[(size_t)v * 8 + (i & 7)] = sScore[i];
    }
}

// -------- per-graph softmax stats --------
__global__ void __launch_bounds__(128) k_segstats() {
    int g = blockIdx.x;
    int s = g_start_arr[g], e = g_start_arr[g + 1];
    __shared__ float red[128];
    __shared__ float sm8[8];
    int tid = threadIdx.x, h = tid & 7, k = tid >> 3;

    float mx = -INFINITY;
    for (int v = s + k; v < e; v += 16) mx = fmaxf(mx, g_scores[(size_t)v * 8 + h]);
    red[tid] = mx;
    __syncthreads();
    for (int st = 64; st >= 8; st >>= 1) {
        if (tid < st) red[tid] = fmaxf(red[tid], red[tid + st]);
        __syncthreads();
    }
    if (tid < 8) {
        float m = red[tid];
        if (!isfinite(m)) m = 0.0f;
        sm8[tid] = m;
        g_m[g * 8 + tid] = m;
    }
    __syncthreads();
    float m = sm8[h];
    float sum = 0.f;
    for (int v = s + k; v < e; v += 16) sum += expf(g_scores[(size_t)v * 8 + h] - m);
    red[tid] = sum;
    __syncthreads();
    for (int st = 64; st >= 8; st >>= 1) {
        if (tid < st) red[tid] += red[tid + st];
        __syncthreads();
    }
    if (tid < 8) g_d[g * 8 + tid] = red[tid];
}

// -------- phase2: out += segsum( softmax_w * relu(hidden @ W2t) ) --------
__global__ void __launch_bounds__(NT, 1) k_transform2(const int* __restrict__ map,
                                                      float* __restrict__ out) {
    extern __shared__ uint8_t smemraw[];
    uint32_t sb = smem_u32(smemraw);
    float* sR = (float*)(smemraw + OFF_SR2);
    __shared__ float swgt[TM * 8];
    __shared__ int smap[TM];
    __shared__ int segStart[TM + 1];
    __shared__ int segGraph[TM];
    __shared__ int nseg;

    int tid = threadIdx.x;
    int m0 = blockIdx.x * TM;

    // async-load hidden tile into A2 (pitch PGA2, natural layout)
    for (int i = tid; i < 4096; i += NT) {
        int row = i >> 5, ch = i & 31;
        int v = m0 + row;
        if (v > V_NODES - 1) v = V_NODES - 1;   // clamp; rows past end never read
        cpa16(sb + (uint32_t)(row * PGA2 + ch * 2) * 8u,
              &g_hidden[(size_t)v * 64 + ch * 2]);
    }
    CP_COMMIT();

    for (int o = tid; o < TM * 8; o += NT) {
        int row = o >> 3, h = o & 7;
        int v = m0 + row;
        float w = 0.f;
        if (v < V_NODES) {
            int gg = map[v];
            if (h == 0) smap[row] = gg;
            float D = g_d[gg * 8 + h];
            if (D > 0.f)
                w = expf(g_scores[(size_t)v * 8 + h] - g_m[gg * 8 + h]) / D;
        } else if (h == 0) {
            smap[row] = -1;
        }
        swgt[o] = w;
    }
    __syncthreads();
    if (tid == 0) {
        int ns = 0, prev = -2, endr = TM;
        for (int r = 0; r < TM; ++r) {
            int mg = smap[r];
            if (mg < 0) { endr = r; break; }
            if (mg != prev) { segStart[ns] = r; segGraph[ns] = mg; prev = mg; ++ns; }
        }
        segStart[ns] = endr;
        nseg = ns;
    }
    CP_WAIT0();
    __syncthreads();

    int lane = tid & 31, wid = tid >> 5, warpM = wid >> 2, warpN = wid & 3;
    int g = lane >> 2, cc = lane & 3;

    float acc0[2][4][4], acc1[2][4][4];
#pragma unroll
    for (int a = 0; a < 2; ++a)
#pragma unroll
        for (int b = 0; b < 4; ++b)
#pragma unroll
            for (int q = 0; q < 4; ++q) { acc0[a][b][q] = 0.f; acc1[a][b][q] = 0.f; }

    gemm_dual<8, PGA2, 0>(sb, g_b2t, g_b2t + 4096, acc0, acc1, lane, warpM, warpN);

#pragma unroll
    for (int half = 0; half < 2; ++half) {
        // relu * softmax-weight -> sR
#pragma unroll
        for (int mt = 0; mt < 2; ++mt)
#pragma unroll
            for (int i2 = 0; i2 < 2; ++i2) {
                int row = warpM * 32 + mt * 16 + i2 * 8 + g;
                float w = swgt[row * 8 + half * 4 + warpN];
#pragma unroll
                for (int nt = 0; nt < 4; ++nt) {
                    int col = warpN * 32 + nt * 8 + cc * 2;
                    float y0 = half ? acc1[mt][nt][2 * i2]     : acc0[mt][nt][2 * i2];
                    float y1 = half ? acc1[mt][nt][2 * i2 + 1] : acc0[mt][nt][2 * i2 + 1];
                    sR[row * 132 + col]     = fmaxf(y0, 0.f) * w;
                    sR[row * 132 + col + 1] = fmaxf(y1, 0.f) * w;
                }
            }
        __syncthreads();

        // segment-reduce rows, one atomic per (segment, col)
        {
            int col = tid & 127, slot = tid >> 7;
            for (int sg = slot; sg < nseg; sg += 4) {
                int r0 = segStart[sg], r1 = segStart[sg + 1];
                float s = 0.f;
                for (int r = r0; r < r1; ++r) s += sR[r * 132 + col];
                atomicAdd(&out[(size_t)segGraph[sg] * GD + half * 128 + col], s);
            }
        }
        __syncthreads();
    }
}

// -------- launch --------
extern "C" void kernel_launch(void* const* d_in, const int* in_sizes, int n_in,
                              void* d_out, int out_size) {
    const float* E   = (const float*)d_in[0];
    const int*   map = (const int*)d_in[1];
    int base = (in_sizes[2] == 1) ? 3 : 2;
    const float* sw1 = (const float*)d_in[base + 0];
    const float* sw2 = (const float*)d_in[base + 1];
    const float* tw1 = (const float*)d_in[base + 2];
    const float* tw2 = (const float*)d_in[base + 3];
    float* out = (float*)d_out;

    cudaFuncSetAttribute(k_main, cudaFuncAttributeMaxDynamicSharedMemorySize,
                         SMEM_MAIN);
    cudaFuncSetAttribute(k_transform2, cudaFuncAttributeMaxDynamicSharedMemorySize,
                         SMEM_TRANS2);

    int nOut = G_NUM * GD;
    int nTiles = (V_NODES + TM - 1) / TM;

    k_zero<<<(nOut + 255) / 256, 256>>>(out, nOut);
    k_offsets<<<(V_NODES + 255) / 256, 256>>>(map);
    k_prep<<<32, 256>>>(sw1, tw1, tw2);
    k_main<<<nTiles, NT, SMEM_MAIN>>>(E, sw2);
    k_segstats<<<G_NUM, 128>>>();
    k_transform2<<<nTiles, NT, SMEM_TRANS2>>>(map, out);
}

// round 10
// speedup vs baseline: 1.2532x; 1.2532x over previous
#include <cuda_runtime.h>
#include <cuda_bf16.h>
#include <math.h>
#include <stdint.h>

#define V_NODES 500000
#define VD 256
#define G_NUM 4000
#define H_HEADS 8
#define GD 256
#define HID 128
#define TM 64
#define NT 256

#define PGA  132   // A1 row pitch in 8B granules (128 k-pairs + 4 pad)
#define PGA2 68    // A2 row pitch (64 k-pairs + 4 pad)
#define SMEM_MAIN   (TM * PGA * 8)                     // 67584
#define OFF_SR2     (TM * PGA2 * 8)                    // 34816
#define SMEM_TRANS2 (OFF_SR2 + TM * 132 * 4)           // 68608

// -------- device scratch --------
__device__ float g_scores[(size_t)V_NODES * H_HEADS];
__device__ float g_m[G_NUM * H_HEADS];
__device__ float g_d[G_NUM * H_HEADS];
__device__ int   g_start_arr[G_NUM + 1];
// hidden_t = relu(E @ W1t) as hi/lo bf16 pairs, phase2-A fragment layout
__device__ uint2 g_hidden[(size_t)V_NODES * 64];
// frag-ordered weight images: entry (ks,n,c) = {bh0, bl0, bh1, bl1}
__device__ uint4 g_b1s[16 * 128 * 4];
__device__ uint4 g_b1t[16 * 128 * 4];
__device__ uint4 g_b2t[2 * 8 * 128 * 4];

// -------- helpers --------
static __device__ __forceinline__ uint32_t smem_u32(const void* p) {
    uint32_t a;
    asm("{ .reg .u64 t; cvta.to.shared.u64 t, %1; cvt.u32.u64 %0, t; }" : "=r"(a) : "l"(p));
    return a;
}
static __device__ __forceinline__ void lds64(uint32_t& a, uint32_t& b, uint32_t addr) {
    asm volatile("ld.shared.v2.b32 {%0,%1}, [%2];" : "=r"(a), "=r"(b) : "r"(addr));
}
static __device__ __forceinline__ void sts64(uint32_t addr, uint32_t a, uint32_t b) {
    asm volatile("st.shared.v2.b32 [%0], {%1,%2};" :: "r"(addr), "r"(a), "r"(b) : "memory");
}
static __device__ __forceinline__ void cpa16(uint32_t s, const void* g) {
    asm volatile("{ .reg .u64 gp; cvta.to.global.u64 gp, %1; "
                 "cp.async.cg.shared.global [%0], [gp], 16; }"
                 :: "r"(s), "l"(g) : "memory");
}
#define CP_COMMIT() asm volatile("cp.async.commit_group;" ::: "memory")
#define CP_WAIT0()  asm volatile("cp.async.wait_group 0;" ::: "memory")

static __device__ __forceinline__ void split2(float x0, float x1, uint32_t& h, uint32_t& l) {
    __nv_bfloat16 h0 = __float2bfloat16(x0), h1 = __float2bfloat16(x1);
    float r0 = x0 - __bfloat162float(h0);
    float r1 = x1 - __bfloat162float(h1);
    __nv_bfloat16 l0 = __float2bfloat16(r0), l1 = __float2bfloat16(r1);
    h = (uint32_t)__bfloat16_as_ushort(h0) | ((uint32_t)__bfloat16_as_ushort(h1) << 16);
    l = (uint32_t)__bfloat16_as_ushort(l0) | ((uint32_t)__bfloat16_as_ushort(l1) << 16);
}
static __device__ __forceinline__ void mma16816(float* d, const uint32_t* a,
                                                uint32_t b0, uint32_t b1) {
    asm volatile("mma.sync.aligned.m16n8k16.row.col.f32.bf16.bf16.f32 "
                 "{%0,%1,%2,%3}, {%4,%5,%6,%7}, {%8,%9}, {%0,%1,%2,%3};"
                 : "+f"(d[0]), "+f"(d[1]), "+f"(d[2]), "+f"(d[3])
                 : "r"(a[0]), "r"(a[1]), "r"(a[2]), "r"(a[3]), "r"(b0), "r"(b1));
}

// Dual-accumulate GEMM with alternate-image B lookahead.
// One pass over A fragments (smem), two B images (LDG), two accumulator sets.
template<int NKS, int PG, int SWZ>
static __device__ __forceinline__ void gemm_dual(uint32_t aB,
                                                 const uint4* __restrict__ b0img,
                                                 const uint4* __restrict__ b1img,
                                                 float (&acc0)[2][4][4],
                                                 float (&acc1)[2][4][4],
                                                 int lane, int warpM, int warpN) {
    const int g = lane >> 2, c = lane & 3;
    const uint4* bp0 = b0img + ((warpN * 32 + g) * 4 + c);
    const uint4* bp1 = b1img + ((warpN * 32 + g) * 4 + c);
    const uint32_t aRow = aB + (uint32_t)((warpM * 32 + g) * PG) * 8u;
    uint4 c0[4];
#pragma unroll
    for (int nt = 0; nt < 4; ++nt) c0[nt] = __ldg(bp0 + nt * 32);
#pragma unroll
    for (int ks = 0; ks < NKS; ++ks) {
        const int x = SWZ ? (ks >> 2) : 0;
        const uint32_t j = (uint32_t)(((ks * 8) + c) ^ x) * 8u;
        uint32_t ah[2][4], al[2][4];
#pragma unroll
        for (int mt = 0; mt < 2; ++mt) {
            uint32_t base = aRow + j + (uint32_t)(mt * PG * 128);
            lds64(ah[mt][0], al[mt][0], base);
            lds64(ah[mt][1], al[mt][1], base + (uint32_t)PG * 64u);
            lds64(ah[mt][2], al[mt][2], base + 32u);
            lds64(ah[mt][3], al[mt][3], base + (uint32_t)PG * 64u + 32u);
        }
        uint4 c1[4];
#pragma unroll
        for (int nt = 0; nt < 4; ++nt) c1[nt] = __ldg(bp1 + ks * 512 + nt * 32);
        // image-0 MMAs cover c1's LDG latency
#pragma unroll
        for (int nt = 0; nt < 4; ++nt)
#pragma unroll
            for (int mt = 0; mt < 2; ++mt) {
                mma16816(acc0[mt][nt], ah[mt], c0[nt].x, c0[nt].z);
                mma16816(acc0[mt][nt], ah[mt], c0[nt].y, c0[nt].w);
                mma16816(acc0[mt][nt], al[mt], c0[nt].x, c0[nt].z);
            }
        if (ks + 1 < NKS) {
#pragma unroll
            for (int nt = 0; nt < 4; ++nt) c0[nt] = __ldg(bp0 + (ks + 1) * 512 + nt * 32);
        }
        // image-1 MMAs cover next c0's LDG latency
#pragma unroll
        for (int nt = 0; nt < 4; ++nt)
#pragma unroll
            for (int mt = 0; mt < 2; ++mt) {
                mma16816(acc1[mt][nt], ah[mt], c1[nt].x, c1[nt].z);
                mma16816(acc1[mt][nt], ah[mt], c1[nt].y, c1[nt].w);
                mma16816(acc1[mt][nt], al[mt], c1[nt].x, c1[nt].z);
            }
    }
}

// stage full TM x 256 E tile as interleaved hi/lo pairs, conflict-free XOR layout
static __device__ __forceinline__ void stageE(const float* __restrict__ E, int m0,
                                              uint32_t aB, int tid) {
    int r = tid >> 2, q4 = tid & 3;
    bool ok = (m0 + r) < V_NODES;
    const float4* src = (const float4*)(E + (size_t)(m0 + r) * VD + q4 * 64);
    uint32_t base = aB + (uint32_t)(r * PGA) * 8u;
#pragma unroll
    for (int t = 0; t < 16; ++t) {
        float4 v = ok ? src[t] : make_float4(0.f, 0.f, 0.f, 0.f);
        int j0 = q4 * 32 + 2 * t;
        uint32_t h, l;
        split2(v.x, v.y, h, l);
        sts64(base + (uint32_t)(j0 ^ q4) * 8u, h, l);
        split2(v.z, v.w, h, l);
        sts64(base + (uint32_t)((j0 + 1) ^ q4) * 8u, h, l);
    }
}

// -------- trivial kernels --------
__global__ void k_zero(float* __restrict__ out, int n) {
    int i = blockIdx.x * blockDim.x + threadIdx.x;
    if (i < n) out[i] = 0.0f;
}
__global__ void k_offsets(const int* __restrict__ map) {
    int v = blockIdx.x * blockDim.x + threadIdx.x;
    if (v >= V_NODES) return;
    int m = map[v];
    int prev = (v == 0) ? -1 : map[v - 1];
    for (int g = prev + 1; g <= m; ++g) g_start_arr[g] = v;
    if (v == V_NODES - 1)
        for (int g = m + 1; g <= G_NUM; ++g) g_start_arr[g] = V_NODES;
}

// build frag-ordered hi/lo bf16 weight images
__global__ void k_prep(const float* __restrict__ sw1,
                       const float* __restrict__ tw1,
                       const float* __restrict__ tw2) {
    int i = blockIdx.x * blockDim.x + threadIdx.x;
    if (i >= 8192) return;
    int ks = i >> 9, n = (i >> 2) & 127, c = i & 3;
    int k0 = ks * 16 + 2 * c;
    uint4 e;
    split2(sw1[(size_t)k0 * HID + n], sw1[(size_t)(k0 + 1) * HID + n], e.x, e.y);
    split2(sw1[(size_t)(k0 + 8) * HID + n], sw1[(size_t)(k0 + 9) * HID + n], e.z, e.w);
    g_b1s[i] = e;
    split2(tw1[(size_t)k0 * HID + n], tw1[(size_t)(k0 + 1) * HID + n], e.x, e.y);
    split2(tw1[(size_t)(k0 + 8) * HID + n], tw1[(size_t)(k0 + 9) * HID + n], e.z, e.w);
    g_b1t[i] = e;
    int half = i >> 12, ks2 = (i >> 9) & 7;
    int ng = half * 128 + n, k2 = ks2 * 16 + 2 * c;
    split2(tw2[(size_t)k2 * GD + ng], tw2[(size_t)(k2 + 1) * GD + ng], e.x, e.y);
    split2(tw2[(size_t)(k2 + 8) * GD + ng], tw2[(size_t)(k2 + 9) * GD + ng], e.z, e.w);
    g_b2t[i] = e;
}

// -------- fused: scores + hidden_t (single A pass, dual accumulators) --------
__global__ void __launch_bounds__(NT, 2) k_main(const float* __restrict__ E,
                                                const float* __restrict__ W2s) {
    extern __shared__ uint8_t smemraw[];
    uint32_t sb = smem_u32(smemraw);
    __shared__ float sW2[HID * 8];
    __shared__ float sScore[TM * 8];
    int tid = threadIdx.x;
    int m0 = blockIdx.x * TM;
    for (int i = tid; i < HID * 8; i += NT) sW2[i] = W2s[i];
    for (int i = tid; i < TM * 8; i += NT) sScore[i] = 0.f;

    stageE(E, m0, sb, tid);

    int lane = tid & 31, wid = tid >> 5, warpM = wid >> 2, warpN = wid & 3;
    int g = lane >> 2, cc = lane & 3;

    float accT[2][4][4], accS[2][4][4];
#pragma unroll
    for (int a = 0; a < 2; ++a)
#pragma unroll
        for (int b = 0; b < 4; ++b)
#pragma unroll
            for (int q = 0; q < 4; ++q) { accT[a][b][q] = 0.f; accS[a][b][q] = 0.f; }
    __syncthreads();

    gemm_dual<16, PGA, 1>(sb, g_b1t, g_b1s, accT, accS, lane, warpM, warpN);

    // ---- hidden_t = relu(accT) -> g_hidden (phase2 frag layout) ----
#pragma unroll
    for (int mt = 0; mt < 2; ++mt)
#pragma unroll
        for (int i2 = 0; i2 < 2; ++i2) {
            int v = m0 + warpM * 32 + mt * 16 + i2 * 8 + g;
            if (v < V_NODES) {
#pragma unroll
                for (int nt = 0; nt < 4; ++nt) {
                    int g2 = warpN * 16 + nt * 4 + cc;
                    float x0 = fmaxf(accT[mt][nt][2 * i2], 0.f);
                    float x1 = fmaxf(accT[mt][nt][2 * i2 + 1], 0.f);
                    uint2 hl;
                    split2(x0, x1, hl.x, hl.y);
                    g_hidden[(size_t)v * 64 + g2] = hl;
                }
            }
        }

    // ---- scores = relu(accS) @ W2s ----
    float p[4][8];
#pragma unroll
    for (int r = 0; r < 4; ++r)
#pragma unroll
        for (int h = 0; h < 8; ++h) p[r][h] = 0.f;
#pragma unroll
    for (int mt = 0; mt < 2; ++mt)
#pragma unroll
        for (int nt = 0; nt < 4; ++nt) {
            int c0 = warpN * 32 + nt * 8 + cc * 2;
            float v0 = fmaxf(accS[mt][nt][0], 0.f), v1 = fmaxf(accS[mt][nt][1], 0.f);
            float v2 = fmaxf(accS[mt][nt][2], 0.f), v3 = fmaxf(accS[mt][nt][3], 0.f);
#pragma unroll
            for (int h = 0; h < 8; ++h) {
                p[mt * 2 + 0][h] += v0 * sW2[c0 * 8 + h] + v1 * sW2[c0 * 8 + 8 + h];
                p[mt * 2 + 1][h] += v2 * sW2[c0 * 8 + h] + v3 * sW2[c0 * 8 + 8 + h];
            }
        }
#pragma unroll
    for (int off = 1; off <= 2; off <<= 1)
#pragma unroll
        for (int r = 0; r < 4; ++r)
#pragma unroll
            for (int h = 0; h < 8; ++h)
                p[r][h] += __shfl_xor_sync(0xFFFFFFFFu, p[r][h], off);
    if (cc == 0) {
#pragma unroll
        for (int mt = 0; mt < 2; ++mt)
#pragma unroll
            for (int i2 = 0; i2 < 2; ++i2) {
                int row = warpM * 32 + mt * 16 + i2 * 8 + g;
#pragma unroll
                for (int h = 0; h < 8; ++h)
                    atomicAdd(&sScore[row * 8 + h], p[mt * 2 + i2][h]);
            }
    }
    __syncthreads();
    for (int i = tid; i < TM * 8; i += NT) {
        int v = m0 + (i >> 3);
        if (v < V_NODES) g_scores[(size_t)v * 8 + (i & 7)] = sScore[i];
    }
}

// -------- per-graph softmax stats --------
__global__ void __launch_bounds__(128) k_segstats() {
    int g = blockIdx.x;
    int s = g_start_arr[g], e = g_start_arr[g + 1];
    __shared__ float red[128];
    __shared__ float sm8[8];
    int tid = threadIdx.x, h = tid & 7, k = tid >> 3;

    float mx = -INFINITY;
    for (int v = s + k; v < e; v += 16) mx = fmaxf(mx, g_scores[(size_t)v * 8 + h]);
    red[tid] = mx;
    __syncthreads();
    for (int st = 64; st >= 8; st >>= 1) {
        if (tid < st) red[tid] = fmaxf(red[tid], red[tid + st]);
        __syncthreads();
    }
    if (tid < 8) {
        float m = red[tid];
        if (!isfinite(m)) m = 0.0f;
        sm8[tid] = m;
        g_m[g * 8 + tid] = m;
    }
    __syncthreads();
    float m = sm8[h];
    float sum = 0.f;
    for (int v = s + k; v < e; v += 16) sum += expf(g_scores[(size_t)v * 8 + h] - m);
    red[tid] = sum;
    __syncthreads();
    for (int st = 64; st >= 8; st >>= 1) {
        if (tid < st) red[tid] += red[tid + st];
        __syncthreads();
    }
    if (tid < 8) g_d[g * 8 + tid] = red[tid];
}

// -------- phase2: out += segsum( softmax_w * relu(hidden @ W2t) ) --------
__global__ void __launch_bounds__(NT, 2) k_transform2(const int* __restrict__ map,
                                                      float* __restrict__ out) {
    extern __shared__ uint8_t smemraw[];
    uint32_t sb = smem_u32(smemraw);
    float* sR = (float*)(smemraw + OFF_SR2);
    __shared__ float swgt[TM * 8];
    __shared__ int smap[TM];
    __shared__ int segStart[TM + 1];
    __shared__ int segGraph[TM];
    __shared__ int nseg;

    int tid = threadIdx.x;
    int m0 = blockIdx.x * TM;

    // async-load hidden tile into A2 (pitch PGA2, natural layout)
    for (int i = tid; i < TM * 32; i += NT) {
        int row = i >> 5, ch = i & 31;
        int v = m0 + row;
        if (v > V_NODES - 1) v = V_NODES - 1;   // clamp; rows past end never read
        cpa16(sb + (uint32_t)(row * PGA2 + ch * 2) * 8u,
              &g_hidden[(size_t)v * 64 + ch * 2]);
    }
    CP_COMMIT();

    for (int o = tid; o < TM * 8; o += NT) {
        int row = o >> 3, h = o & 7;
        int v = m0 + row;
        float w = 0.f;
        if (v < V_NODES) {
            int gg = map[v];
            if (h == 0) smap[row] = gg;
            float D = g_d[gg * 8 + h];
            if (D > 0.f)
                w = expf(g_scores[(size_t)v * 8 + h] - g_m[gg * 8 + h]) / D;
        } else if (h == 0) {
            smap[row] = -1;
        }
        swgt[o] = w;
    }
    __syncthreads();
    if (tid == 0) {
        int ns = 0, prev = -2, endr = TM;
        for (int r = 0; r < TM; ++r) {
            int mg = smap[r];
            if (mg < 0) { endr = r; break; }
            if (mg != prev) { segStart[ns] = r; segGraph[ns] = mg; prev = mg; ++ns; }
        }
        segStart[ns] = endr;
        nseg = ns;
    }
    CP_WAIT0();
    __syncthreads();

    int lane = tid & 31, wid = tid >> 5, warpM = wid >> 2, warpN = wid & 3;
    int g = lane >> 2, cc = lane & 3;

    float acc0[2][4][4], acc1[2][4][4];
#pragma unroll
    for (int a = 0; a < 2; ++a)
#pragma unroll
        for (int b = 0; b < 4; ++b)
#pragma unroll
            for (int q = 0; q < 4; ++q) { acc0[a][b][q] = 0.f; acc1[a][b][q] = 0.f; }

    gemm_dual<8, PGA2, 0>(sb, g_b2t, g_b2t + 4096, acc0, acc1, lane, warpM, warpN);

#pragma unroll
    for (int half = 0; half < 2; ++half) {
        // relu * softmax-weight -> sR
#pragma unroll
        for (int mt = 0; mt < 2; ++mt)
#pragma unroll
            for (int i2 = 0; i2 < 2; ++i2) {
                int row = warpM * 32 + mt * 16 + i2 * 8 + g;
                float w = swgt[row * 8 + half * 4 + warpN];
#pragma unroll
                for (int nt = 0; nt < 4; ++nt) {
                    int col = warpN * 32 + nt * 8 + cc * 2;
                    float y0 = half ? acc1[mt][nt][2 * i2]     : acc0[mt][nt][2 * i2];
                    float y1 = half ? acc1[mt][nt][2 * i2 + 1] : acc0[mt][nt][2 * i2 + 1];
                    sR[row * 132 + col]     = fmaxf(y0, 0.f) * w;
                    sR[row * 132 + col + 1] = fmaxf(y1, 0.f) * w;
                }
            }
        __syncthreads();

        // segment-reduce rows, one atomic per (segment, col)
        {
            int col = tid & 127, slot = tid >> 7;
            for (int sg = slot; sg < nseg; sg += 2) {
                int r0 = segStart[sg], r1 = segStart[sg + 1];
                float s = 0.f;
                for (int r = r0; r < r1; ++r) s += sR[r * 132 + col];
                atomicAdd(&out[(size_t)segGraph[sg] * GD + half * 128 + col], s);
            }
        }
        __syncthreads();
    }
}

// -------- launch --------
extern "C" void kernel_launch(void* const* d_in, const int* in_sizes, int n_in,
                              void* d_out, int out_size) {
    const float* E   = (const float*)d_in[0];
    const int*   map = (const int*)d_in[1];
    int base = (in_sizes[2] == 1) ? 3 : 2;
    const float* sw1 = (const float*)d_in[base + 0];
    const float* sw2 = (const float*)d_in[base + 1];
    const float* tw1 = (const float*)d_in[base + 2];
    const float* tw2 = (const float*)d_in[base + 3];
    float* out = (float*)d_out;

    cudaFuncSetAttribute(k_main, cudaFuncAttributeMaxDynamicSharedMemorySize,
                         SMEM_MAIN);
    cudaFuncSetAttribute(k_transform2, cudaFuncAttributeMaxDynamicSharedMemorySize,
                         SMEM_TRANS2);

    int nOut = G_NUM * GD;
    int nTiles = (V_NODES + TM - 1) / TM;

    k_zero<<<(nOut + 255) / 256, 256>>>(out, nOut);
    k_offsets<<<(V_NODES + 255) / 256, 256>>>(map);
    k_prep<<<32, 256>>>(sw1, tw1, tw2);
    k_main<<<nTiles, NT, SMEM_MAIN>>>(E, sw2);
    k_segstats<<<G_NUM, 128>>>();
    k_transform2<<<nTiles, NT, SMEM_TRANS2>>>(map, out);
}

// round 11
// speedup vs baseline: 1.2727x; 1.0156x over previous
#include <cuda_runtime.h>
#include <cuda_bf16.h>
#include <math.h>
#include <stdint.h>

#define V_NODES 500000
#define VD 256
#define G_NUM 4000
#define H_HEADS 8
#define GD 256
#define HID 128
#define TM 64
#define NT 256

#define PGA  136   // A1 row pitch in 8B granules (1088B; 16B-slot shift 4/row)
#define PGA2 72    // A2 row pitch (576B; same shift property)
#define SMEM_MAIN   (TM * PGA * 8)                     // 69632
#define OFF_SR2     (TM * PGA2 * 8)                    // 36864
#define SMEM_TRANS2 (OFF_SR2 + TM * 132 * 4)           // 70656

// -------- device scratch --------
__device__ float g_scores[(size_t)V_NODES * H_HEADS];
__device__ float g_m[G_NUM * H_HEADS];
__device__ float g_d[G_NUM * H_HEADS];
__device__ int   g_start_arr[G_NUM + 1];
// hidden_t = relu(E @ W1t), hi/lo bf16 pairs, permuted+swizzled frag layout
__device__ uint2 g_hidden[(size_t)V_NODES * 64];
// frag-ordered weight images: entry (ks,n,c) = {bh0, bl0, bh1, bl1}
__device__ uint4 g_b1s[16 * 128 * 4];
__device__ uint4 g_b1t[16 * 128 * 4];
__device__ uint4 g_b2t[2 * 8 * 128 * 4];

// -------- helpers --------
static __device__ __forceinline__ uint32_t smem_u32(const void* p) {
    uint32_t a;
    asm("{ .reg .u64 t; cvta.to.shared.u64 t, %1; cvt.u32.u64 %0, t; }" : "=r"(a) : "l"(p));
    return a;
}
static __device__ __forceinline__ void lds128(uint32_t& a, uint32_t& b,
                                              uint32_t& c, uint32_t& d, uint32_t addr) {
    asm volatile("ld.shared.v4.b32 {%0,%1,%2,%3}, [%4];"
                 : "=r"(a), "=r"(b), "=r"(c), "=r"(d) : "r"(addr));
}
static __device__ __forceinline__ void sts64(uint32_t addr, uint32_t a, uint32_t b) {
    asm volatile("st.shared.v2.b32 [%0], {%1,%2};" :: "r"(addr), "r"(a), "r"(b) : "memory");
}
static __device__ __forceinline__ void cpa16(uint32_t s, const void* g) {
    asm volatile("{ .reg .u64 gp; cvta.to.global.u64 gp, %1; "
                 "cp.async.cg.shared.global [%0], [gp], 16; }"
                 :: "r"(s), "l"(g) : "memory");
}
#define CP_COMMIT() asm volatile("cp.async.commit_group;" ::: "memory")
#define CP_WAIT0()  asm volatile("cp.async.wait_group 0;" ::: "memory")

// truncation-based hi/lo bf16 split: hi = top16(x) (PRMT pack), lo = bf16(x - hi)
static __device__ __forceinline__ void split2(float x0, float x1, uint32_t& h, uint32_t& l) {
    uint32_t u0 = __float_as_uint(x0), u1 = __float_as_uint(x1);
    float t0 = __uint_as_float(u0 & 0xFFFF0000u);
    float t1 = __uint_as_float(u1 & 0xFFFF0000u);
    float r0 = x0 - t0, r1 = x1 - t1;
    asm("prmt.b32 %0, %1, %2, 0x7632;" : "=r"(h) : "r"(u0), "r"(u1));
    asm("cvt.rn.bf16x2.f32 %0, %1, %2;" : "=r"(l) : "f"(r1), "f"(r0));
}
static __device__ __forceinline__ void mma16816(float* d, const uint32_t* a,
                                                uint32_t b0, uint32_t b1) {
    asm volatile("mma.sync.aligned.m16n8k16.row.col.f32.bf16.bf16.f32 "
                 "{%0,%1,%2,%3}, {%4,%5,%6,%7}, {%8,%9}, {%0,%1,%2,%3};"
                 : "+f"(d[0]), "+f"(d[1]), "+f"(d[2]), "+f"(d[3])
                 : "r"(a[0]), "r"(a[1]), "r"(a[2]), "r"(a[3]), "r"(b0), "r"(b1));
}

// granule position for k-pair j: octet-internal perm (pair c and c+4 adjacent)
// + XOR 2*(j>>5) on bits 1-2. Compile-time when j is constant.
static __device__ __forceinline__ int gpos(int j) {
    int w = j & 7;
    int p = ((w & 3) << 1) | (w >> 2);
    return ((j & ~7) | p) ^ (2 * (j >> 5));
}

// Dual-accumulate GEMM: A via conflict-free lds128 fragments, B via LDG from
// frag-ordered images with one-ks lookahead on image 0.
template<int NKS, int PG>
static __device__ __forceinline__ void gemm_dual(uint32_t aB,
                                                 const uint4* __restrict__ b0img,
                                                 const uint4* __restrict__ b1img,
                                                 float (&acc0)[2][4][4],
                                                 float (&acc1)[2][4][4],
                                                 int lane, int warpM, int warpN) {
    const int g = lane >> 2, c = lane & 3;
    const uint4* bp0 = b0img + ((warpN * 32 + g) * 4 + c);
    const uint4* bp1 = b1img + ((warpN * 32 + g) * 4 + c);
    const uint32_t rowA = aB + (uint32_t)((warpM * 32 + g) * PG) * 8u;
    uint4 c0[4];
#pragma unroll
    for (int nt = 0; nt < 4; ++nt) c0[nt] = __ldg(bp0 + nt * 32);
#pragma unroll
    for (int ks = 0; ks < NKS; ++ks) {
        const uint32_t j16 = (uint32_t)(((ks * 4 + c) ^ (ks >> 2)) * 16);
        uint32_t ah[2][4], al[2][4];
#pragma unroll
        for (int mt = 0; mt < 2; ++mt) {
            uint32_t b0a = rowA + (uint32_t)(mt * PG * 128) + j16;
            lds128(ah[mt][0], al[mt][0], ah[mt][2], al[mt][2], b0a);
            lds128(ah[mt][1], al[mt][1], ah[mt][3], al[mt][3], b0a + (uint32_t)PG * 64u);
        }
        uint4 c1[4];
#pragma unroll
        for (int nt = 0; nt < 4; ++nt) c1[nt] = __ldg(bp1 + ks * 512 + nt * 32);
        // image-0 MMAs (cover c1 latency)
#pragma unroll
        for (int nt = 0; nt < 4; ++nt)
#pragma unroll
            for (int mt = 0; mt < 2; ++mt) {
                mma16816(acc0[mt][nt], ah[mt], c0[nt].x, c0[nt].z);
                mma16816(acc0[mt][nt], ah[mt], c0[nt].y, c0[nt].w);
                mma16816(acc0[mt][nt], al[mt], c0[nt].x, c0[nt].z);
            }
        if (ks + 1 < NKS) {
#pragma unroll
            for (int nt = 0; nt < 4; ++nt) c0[nt] = __ldg(bp0 + (ks + 1) * 512 + nt * 32);
        }
        // image-1 MMAs (cover next c0 latency)
#pragma unroll
        for (int nt = 0; nt < 4; ++nt)
#pragma unroll
            for (int mt = 0; mt < 2; ++mt) {
                mma16816(acc1[mt][nt], ah[mt], c1[nt].x, c1[nt].z);
                mma16816(acc1[mt][nt], ah[mt], c1[nt].y, c1[nt].w);
                mma16816(acc1[mt][nt], al[mt], c1[nt].x, c1[nt].z);
            }
    }
}

// stage TM x 256 E tile: hi/lo pairs at permuted+swizzled granule positions
static __device__ __forceinline__ void stageE(const float* __restrict__ E, int m0,
                                              uint32_t aB, int tid) {
    int r = tid >> 2, q4 = tid & 3;
    bool ok = (m0 + r) < V_NODES;
    const float4* src = (const float4*)(E + (size_t)(m0 + r) * VD + q4 * 64);
    uint32_t base = aB + (uint32_t)(r * PGA) * 8u;
#pragma unroll
    for (int t = 0; t < 16; ++t) {
        float4 v = ok ? src[t] : make_float4(0.f, 0.f, 0.f, 0.f);
        int j0 = q4 * 32 + 2 * t;
        uint32_t h, l;
        split2(v.x, v.y, h, l);
        sts64(base + (uint32_t)gpos(j0) * 8u, h, l);
        split2(v.z, v.w, h, l);
        sts64(base + (uint32_t)gpos(j0 + 1) * 8u, h, l);
    }
}

// -------- trivial kernels --------
__global__ void k_zero(float* __restrict__ out, int n) {
    int i = blockIdx.x * blockDim.x + threadIdx.x;
    if (i < n) out[i] = 0.0f;
}
__global__ void k_offsets(const int* __restrict__ map) {
    int v = blockIdx.x * blockDim.x + threadIdx.x;
    if (v >= V_NODES) return;
    int m = map[v];
    int prev = (v == 0) ? -1 : map[v - 1];
    for (int g = prev + 1; g <= m; ++g) g_start_arr[g] = v;
    if (v == V_NODES - 1)
        for (int g = m + 1; g <= G_NUM; ++g) g_start_arr[g] = V_NODES;
}

// build frag-ordered hi/lo bf16 weight images
__global__ void k_prep(const float* __restrict__ sw1,
                       const float* __restrict__ tw1,
                       const float* __restrict__ tw2) {
    int i = blockIdx.x * blockDim.x + threadIdx.x;
    if (i >= 8192) return;
    int ks = i >> 9, n = (i >> 2) & 127, c = i & 3;
    int k0 = ks * 16 + 2 * c;
    uint4 e;
    split2(sw1[(size_t)k0 * HID + n], sw1[(size_t)(k0 + 1) * HID + n], e.x, e.y);
    split2(sw1[(size_t)(k0 + 8) * HID + n], sw1[(size_t)(k0 + 9) * HID + n], e.z, e.w);
    g_b1s[i] = e;
    split2(tw1[(size_t)k0 * HID + n], tw1[(size_t)(k0 + 1) * HID + n], e.x, e.y);
    split2(tw1[(size_t)(k0 + 8) * HID + n], tw1[(size_t)(k0 + 9) * HID + n], e.z, e.w);
    g_b1t[i] = e;
    int half = i >> 12, ks2 = (i >> 9) & 7;
    int ng = half * 128 + n, k2 = ks2 * 16 + 2 * c;
    split2(tw2[(size_t)k2 * GD + ng], tw2[(size_t)(k2 + 1) * GD + ng], e.x, e.y);
    split2(tw2[(size_t)(k2 + 8) * GD + ng], tw2[(size_t)(k2 + 9) * GD + ng], e.z, e.w);
    g_b2t[i] = e;
}

// -------- fused: scores + hidden_t --------
__global__ void __launch_bounds__(NT, 2) k_main(const float* __restrict__ E,
                                                const float* __restrict__ W2s) {
    extern __shared__ uint8_t smemraw[];
    uint32_t sb = smem_u32(smemraw);
    __shared__ float sW2[HID * 8];
    __shared__ float sScore[TM * 8];
    int tid = threadIdx.x;
    int m0 = blockIdx.x * TM;
    for (int i = tid; i < HID * 8; i += NT) sW2[i] = W2s[i];
    for (int i = tid; i < TM * 8; i += NT) sScore[i] = 0.f;

    stageE(E, m0, sb, tid);

    int lane = tid & 31, wid = tid >> 5, warpM = wid >> 2, warpN = wid & 3;
    int g = lane >> 2, cc = lane & 3;

    float accT[2][4][4], accS[2][4][4];
#pragma unroll
    for (int a = 0; a < 2; ++a)
#pragma unroll
        for (int b = 0; b < 4; ++b)
#pragma unroll
            for (int q = 0; q < 4; ++q) { accT[a][b][q] = 0.f; accS[a][b][q] = 0.f; }
    __syncthreads();

    gemm_dual<16, PGA>(sb, g_b1t, g_b1s, accT, accS, lane, warpM, warpN);

    // ---- hidden_t = relu(accT) -> g_hidden (permuted frag layout) ----
#pragma unroll
    for (int mt = 0; mt < 2; ++mt)
#pragma unroll
        for (int i2 = 0; i2 < 2; ++i2) {
            int v = m0 + warpM * 32 + mt * 16 + i2 * 8 + g;
            if (v < V_NODES) {
#pragma unroll
                for (int nt = 0; nt < 4; ++nt) {
                    int g2 = warpN * 16 + nt * 4 + cc;
                    float x0 = fmaxf(accT[mt][nt][2 * i2], 0.f);
                    float x1 = fmaxf(accT[mt][nt][2 * i2 + 1], 0.f);
                    uint2 hl;
                    split2(x0, x1, hl.x, hl.y);
                    g_hidden[(size_t)v * 64 + gpos(g2)] = hl;
                }
            }
        }

    // ---- scores = relu(accS) @ W2s ----
    float p[4][8];
#pragma unroll
    for (int r = 0; r < 4; ++r)
#pragma unroll
        for (int h = 0; h < 8; ++h) p[r][h] = 0.f;
#pragma unroll
    for (int mt = 0; mt < 2; ++mt)
#pragma unroll
        for (int nt = 0; nt < 4; ++nt) {
            int c0 = warpN * 32 + nt * 8 + cc * 2;
            float v0 = fmaxf(accS[mt][nt][0], 0.f), v1 = fmaxf(accS[mt][nt][1], 0.f);
            float v2 = fmaxf(accS[mt][nt][2], 0.f), v3 = fmaxf(accS[mt][nt][3], 0.f);
#pragma unroll
            for (int h = 0; h < 8; ++h) {
                p[mt * 2 + 0][h] += v0 * sW2[c0 * 8 + h] + v1 * sW2[c0 * 8 + 8 + h];
                p[mt * 2 + 1][h] += v2 * sW2[c0 * 8 + h] + v3 * sW2[c0 * 8 + 8 + h];
            }
        }
#pragma unroll
    for (int off = 1; off <= 2; off <<= 1)
#pragma unroll
        for (int r = 0; r < 4; ++r)
#pragma unroll
            for (int h = 0; h < 8; ++h)
                p[r][h] += __shfl_xor_sync(0xFFFFFFFFu, p[r][h], off);
    if (cc == 0) {
#pragma unroll
        for (int mt = 0; mt < 2; ++mt)
#pragma unroll
            for (int i2 = 0; i2 < 2; ++i2) {
                int row = warpM * 32 + mt * 16 + i2 * 8 + g;
#pragma unroll
                for (int h = 0; h < 8; ++h)
                    atomicAdd(&sScore[row * 8 + h], p[mt * 2 + i2][h]);
            }
    }
    __syncthreads();
    for (int i = tid; i < TM * 8; i += NT) {
        int v = m0 + (i >> 3);
        if (v < V_NODES) g_scores[(size_t)v * 8 + (i & 7)] = sScore[i];
    }
}

// -------- per-graph softmax stats --------
__global__ void __launch_bounds__(128) k_segstats() {
    int g = blockIdx.x;
    int s = g_start_arr[g], e = g_start_arr[g + 1];
    __shared__ float red[128];
    __shared__ float sm8[8];
    int tid = threadIdx.x, h = tid & 7, k = tid >> 3;

    float mx = -INFINITY;
    for (int v = s + k; v < e; v += 16) mx = fmaxf(mx, g_scores[(size_t)v * 8 + h]);
    red[tid] = mx;
    __syncthreads();
    for (int st = 64; st >= 8; st >>= 1) {
        if (tid < st) red[tid] = fmaxf(red[tid], red[tid + st]);
        __syncthreads();
    }
    if (tid < 8) {
        float m = red[tid];
        if (!isfinite(m)) m = 0.0f;
        sm8[tid] = m;
        g_m[g * 8 + tid] = m;
    }
    __syncthreads();
    float m = sm8[h];
    float sum = 0.f;
    for (int v = s + k; v < e; v += 16) sum += expf(g_scores[(size_t)v * 8 + h] - m);
    red[tid] = sum;
    __syncthreads();
    for (int st = 64; st >= 8; st >>= 1) {
        if (tid < st) red[tid] += red[tid + st];
        __syncthreads();
    }
    if (tid < 8) g_d[g * 8 + tid] = red[tid];
}

// -------- phase2: out += segsum( softmax_w * relu(hidden @ W2t) ) --------
__global__ void __launch_bounds__(NT, 2) k_transform2(const int* __restrict__ map,
                                                      float* __restrict__ out) {
    extern __shared__ uint8_t smemraw[];
    uint32_t sb = smem_u32(smemraw);
    float* sR = (float*)(smemraw + OFF_SR2);
    __shared__ float swgt[TM * 8];
    __shared__ int smap[TM];
    __shared__ int segStart[TM + 1];
    __shared__ int segGraph[TM];
    __shared__ int nseg;

    int tid = threadIdx.x;
    int m0 = blockIdx.x * TM;

    // async-load hidden tile into A2 (pitch PGA2; data already permuted)
    for (int i = tid; i < TM * 32; i += NT) {
        int row = i >> 5, ch = i & 31;
        int v = m0 + row;
        if (v > V_NODES - 1) v = V_NODES - 1;   // clamp; rows past end never used
        cpa16(sb + (uint32_t)(row * PGA2 + ch * 2) * 8u,
              &g_hidden[(size_t)v * 64 + ch * 2]);
    }
    CP_COMMIT();

    for (int o = tid; o < TM * 8; o += NT) {
        int row = o >> 3, h = o & 7;
        int v = m0 + row;
        float w = 0.f;
        if (v < V_NODES) {
            int gg = map[v];
            if (h == 0) smap[row] = gg;
            float D = g_d[gg * 8 + h];
            if (D > 0.f)
                w = expf(g_scores[(size_t)v * 8 + h] - g_m[gg * 8 + h]) / D;
        } else if (h == 0) {
            smap[row] = -1;
        }
        swgt[o] = w;
    }
    __syncthreads();
    if (tid == 0) {
        int ns = 0, prev = -2, endr = TM;
        for (int r = 0; r < TM; ++r) {
            int mg = smap[r];
            if (mg < 0) { endr = r; break; }
            if (mg != prev) { segStart[ns] = r; segGraph[ns] = mg; prev = mg; ++ns; }
        }
        segStart[ns] = endr;
        nseg = ns;
    }
    CP_WAIT0();
    __syncthreads();

    int lane = tid & 31, wid = tid >> 5, warpM = wid >> 2, warpN = wid & 3;
    int g = lane >> 2, cc = lane & 3;

    float acc0[2][4][4], acc1[2][4][4];
#pragma unroll
    for (int a = 0; a < 2; ++a)
#pragma unroll
        for (int b = 0; b < 4; ++b)
#pragma unroll
            for (int q = 0; q < 4; ++q) { acc0[a][b][q] = 0.f; acc1[a][b][q] = 0.f; }

    gemm_dual<8, PGA2>(sb, g_b2t, g_b2t + 4096, acc0, acc1, lane, warpM, warpN);

#pragma unroll
    for (int half = 0; half < 2; ++half) {
        // relu * softmax-weight -> sR
#pragma unroll
        for (int mt = 0; mt < 2; ++mt)
#pragma unroll
            for (int i2 = 0; i2 < 2; ++i2) {
                int row = warpM * 32 + mt * 16 + i2 * 8 + g;
                float w = swgt[row * 8 + half * 4 + warpN];
#pragma unroll
                for (int nt = 0; nt < 4; ++nt) {
                    int col = warpN * 32 + nt * 8 + cc * 2;
                    float y0 = half ? acc1[mt][nt][2 * i2]     : acc0[mt][nt][2 * i2];
                    float y1 = half ? acc1[mt][nt][2 * i2 + 1] : acc0[mt][nt][2 * i2 + 1];
                    sR[row * 132 + col]     = fmaxf(y0, 0.f) * w;
                    sR[row * 132 + col + 1] = fmaxf(y1, 0.f) * w;
                }
            }
        __syncthreads();

        // segment-reduce rows, one atomic per (segment, col)
        {
            int col = tid & 127, slot = tid >> 7;
            for (int sg = slot; sg < nseg; sg += 2) {
                int r0 = segStart[sg], r1 = segStart[sg + 1];
                float s = 0.f;
                for (int r = r0; r < r1; ++r) s += sR[r * 132 + col];
                atomicAdd(&out[(size_t)segGraph[sg] * GD + half * 128 + col], s);
            }
        }
        __syncthreads();
    }
}

// -------- launch --------
extern "C" void kernel_launch(void* const* d_in, const int* in_sizes, int n_in,
                              void* d_out, int out_size) {
    const float* E   = (const float*)d_in[0];
    const int*   map = (const int*)d_in[1];
    int base = (in_sizes[2] == 1) ? 3 : 2;
    const float* sw1 = (const float*)d_in[base + 0];
    const float* sw2 = (const float*)d_in[base + 1];
    const float* tw1 = (const float*)d_in[base + 2];
    const float* tw2 = (const float*)d_in[base + 3];
    float* out = (float*)d_out;

    cudaFuncSetAttribute(k_main, cudaFuncAttributeMaxDynamicSharedMemorySize,
                         SMEM_MAIN);
    cudaFuncSetAttribute(k_transform2, cudaFuncAttributeMaxDynamicSharedMemorySize,
                         SMEM_TRANS2);

    int nOut = G_NUM * GD;
    int nTiles = (V_NODES + TM - 1) / TM;

    k_zero<<<(nOut + 255) / 256, 256>>>(out, nOut);
    k_offsets<<<(V_NODES + 255) / 256, 256>>>(map);
    k_prep<<<32, 256>>>(sw1, tw1, tw2);
    k_main<<<nTiles, NT, SMEM_MAIN>>>(E, sw2);
    k_segstats<<<G_NUM, 128>>>();
    k_transform2<<<nTiles, NT, SMEM_TRANS2>>>(map, out);
}